// round 9
// baseline (speedup 1.0000x reference)
#include <cuda_runtime.h>
#include <cuda_fp16.h>
#include <stdint.h>

#define B_  4
#define H_  16
#define S_  2048
#define DK_ 64
#define MT  128     // q rows per CTA
#define KT  128     // k rows per smem tile (computed in two 64-col halves)
#define NTHR 256    // 8 warps, 16 q-rows each
#define ROWH 72     // padded row pitch in halves (144B)

// ---------------- static scratch ----------------
#define NEL ((size_t)B_ * H_ * S_ * DK_)            // 8.4M
__device__ __align__(16) __half g_qh[NEL], g_ql[NEL];
__device__ __align__(16) __half g_kh[NEL];
__device__ __align__(16) __half g_vh[NEL];
__device__ __align__(16) __half g_escr[(size_t)B_ * H_ * S_ * S_];     // 512MB unnormalized e (fp16)
__device__ __align__(16) unsigned long long g_maskbits[(size_t)B_ * S_ * (S_ / 64)];

// ---------------- helpers ----------------
__device__ __forceinline__ uint32_t pack2(float a, float b) {
    __half2 h = __floats2half2_rn(a, b);
    return *reinterpret_cast<uint32_t*>(&h);
}
__device__ __forceinline__ float2 unpack2(uint32_t u) {
    __half2 h = *reinterpret_cast<__half2*>(&u);
    return __half22float2(h);
}
__device__ __forceinline__ void cp16(uint32_t dst, const void* src) {
    asm volatile("cp.async.cg.shared.global [%0], [%1], 16;" :: "r"(dst), "l"(src));
}
#define CP_COMMIT() asm volatile("cp.async.commit_group;" ::: "memory")
#define CP_WAIT1()  asm volatile("cp.async.wait_group 1;" ::: "memory")

#define LDSM4(r, a) \
    asm volatile("ldmatrix.sync.aligned.m8n8.x4.shared.b16 {%0,%1,%2,%3}, [%4];" \
        : "=r"((r)[0]), "=r"((r)[1]), "=r"((r)[2]), "=r"((r)[3]) : "r"(a))
#define LDSM4T(r, a) \
    asm volatile("ldmatrix.sync.aligned.m8n8.x4.trans.shared.b16 {%0,%1,%2,%3}, [%4];" \
        : "=r"((r)[0]), "=r"((r)[1]), "=r"((r)[2]), "=r"((r)[3]) : "r"(a))
#define MMA16816(c, a, b0, b1) \
    asm volatile("mma.sync.aligned.m16n8k16.row.col.f32.f16.f16.f32 " \
        "{%0,%1,%2,%3},{%4,%5,%6,%7},{%8,%9},{%0,%1,%2,%3};" \
        : "+f"((c)[0]), "+f"((c)[1]), "+f"((c)[2]), "+f"((c)[3]) \
        : "r"((a)[0]), "r"((a)[1]), "r"((a)[2]), "r"((a)[3]), "r"(b0), "r"(b1))

// smem layout in halves: Qh | Ql | 2 x {Kh[128][72], Vh[128][72]}, then zr[128] floats
#define OFF_QH 0
#define OFF_QL 9216
#define OFF_BUF 18432
#define BUF_SZ  18432      // per buffer: Kh 9216 + Vh 9216 halves
#define OFF_ZR  ((OFF_BUF + 2 * BUF_SZ) * 2)       // byte offset: 110592
#define SMEM_BYTES (OFF_ZR + MT * 4)               // 111104 B

// ================= prep: Q -> fp16 hi/lo (x0.125), K/V -> fp16, mask -> bits ==========
__global__ void prep_kernel(const float4* __restrict__ Q, const float4* __restrict__ K,
                            const float4* __restrict__ V, const unsigned int* __restrict__ m)
{
    const int tid = threadIdx.x;
    if (blockIdx.x < 512) {
        const size_t n = NEL / 4;
        for (size_t i = (size_t)blockIdx.x * 256 + tid; i < n; i += 512 * 256) {
            float4 q = Q[i];
            q.x *= 0.125f; q.y *= 0.125f; q.z *= 0.125f; q.w *= 0.125f;
            uint32_t h0 = pack2(q.x, q.y), h1 = pack2(q.z, q.w);
            float2 a0 = unpack2(h0), a1 = unpack2(h1);
            *(uint2*)(g_qh + 4 * i) = make_uint2(h0, h1);
            *(uint2*)(g_ql + 4 * i) = make_uint2(pack2(q.x - a0.x, q.y - a0.y),
                                                 pack2(q.z - a1.x, q.w - a1.y));
            float4 k = K[i];
            *(uint2*)(g_kh + 4 * i) = make_uint2(pack2(k.x, k.y), pack2(k.z, k.w));
            float4 v = V[i];
            *(uint2*)(g_vh + 4 * i) = make_uint2(pack2(v.x, v.y), pack2(v.z, v.w));
        }
    } else {
        __shared__ int bad01_s, isfloat_s;
        if (tid == 0) { bad01_s = 0; isfloat_s = 1; }
        __syncthreads();
        int bad01 = 0;
        for (int i = tid; i < 4096; i += 256)
            if (m[i] > 1u) bad01 = 1;
        if (bad01) atomicExch(&bad01_s, 1);
        __syncthreads();
        if (bad01_s) {
            int notf = 0;
            for (int i = tid; i < 4096; i += 256) {
                unsigned v = m[i];
                if (v != 0u && v != 0x3F800000u) notf = 1;
            }
            if (notf) atomicExch(&isfloat_s, 0);
        }
        __syncthreads();
        const bool bytemask = bad01_s && !isfloat_s;
        const size_t n = (size_t)B_ * S_ * (S_ / 64);
        for (size_t i = (size_t)(blockIdx.x - 512) * 256 + tid; i < n; i += 512 * 256) {
            unsigned long long bits = 0ull;
            if (bytemask) {
                const uint4* p = (const uint4*)((const unsigned char*)m + i * 64);
                #pragma unroll
                for (int j = 0; j < 4; j++) {
                    uint4 v = p[j];
                    unsigned w[4] = {v.x, v.y, v.z, v.w};
                    #pragma unroll
                    for (int q = 0; q < 4; q++)
                        #pragma unroll
                        for (int bb = 0; bb < 4; bb++)
                            bits |= (unsigned long long)(((w[q] >> (8 * bb)) & 0xffu) == 0u)
                                    << (j * 16 + q * 4 + bb);
                }
            } else {
                const uint4* p = (const uint4*)m + i * 16;
                #pragma unroll
                for (int j = 0; j < 16; j++) {
                    uint4 v = p[j];
                    bits |= ((unsigned long long)(v.x == 0u) << (4 * j))
                          | ((unsigned long long)(v.y == 0u) << (4 * j + 1))
                          | ((unsigned long long)(v.z == 0u) << (4 * j + 2))
                          | ((unsigned long long)(v.w == 0u) << (4 * j + 3));
                }
            }
            g_maskbits[i] = bits;
        }
    }
}

// ================= fused: flash -> ctx + e.fp16, then normalize own slice =================
__global__ void __launch_bounds__(NTHR, 1)
attn_main(float* __restrict__ ctx_out, float* __restrict__ attn_out)
{
    extern __shared__ __half shm[];
    float* zr = (float*)((char*)shm + OFF_ZR);
    const uint32_t sb = (uint32_t)__cvta_generic_to_shared(shm);

    const int tid = threadIdx.x, wid = tid >> 5, lane = tid & 31;
    const int r = lane >> 2, qc = lane & 3;
    const int m0 = 16 * wid;
    const int arow = lane & 15;
    const int akof = (lane >> 4) << 3;
    const int nlaneK = (lane & 7) + ((lane & 16) >> 1);
    const int klaneK = lane & 8;
    const int klaneV = lane & 15;
    const int nlaneV = (lane >> 4) << 3;

    const int q0 = blockIdx.x * MT;
    const size_t bh = (size_t)blockIdx.z * H_ + blockIdx.y;
    const size_t kvbase = bh * S_ * DK_;

    const int gr0 = q0 + m0 + r, gr1 = gr0 + 8;
    const unsigned long long* mbp = g_maskbits + (size_t)blockIdx.z * S_ * (S_ / 64);
    const __half* kvsrc[2] = {g_kh + kvbase, g_vh + kvbase};
    __half* ep0 = g_escr + (bh * S_ + gr0) * (size_t)S_;
    __half* ep1 = g_escr + (bh * S_ + gr1) * (size_t)S_;

    // ---- issue Q + tile 0 loads ----
    {
        const size_t qrow0 = bh * S_ + q0;
        #pragma unroll
        for (int it = 0; it < 8; it++) {
            int i = tid + it * NTHR;           // 0..2047: Qh then Ql
            int arr = i >> 10, rem = i & 1023, row = rem >> 3, c8 = rem & 7;
            const __half* src = (arr ? g_ql : g_qh) + (qrow0 + row) * DK_ + c8 * 8;
            cp16(sb + ((arr ? OFF_QL : OFF_QH) + row * ROWH + c8 * 8) * 2, src);
        }
        #pragma unroll
        for (int it = 0; it < 8; it++) {
            int i = tid + it * NTHR;           // 0..2047: {Kh,Vh} x 128 rows x 8 chunks
            int arr = i >> 10, rem = i & 1023, row = rem >> 3, c8 = rem & 7;
            cp16(sb + (OFF_BUF + arr * 9216 + row * ROWH + c8 * 8) * 2,
                 kvsrc[arr] + (size_t)row * DK_ + c8 * 8);
        }
        CP_COMMIT();
    }

    float ctx[8][4];
    #pragma unroll
    for (int j = 0; j < 8; j++)
        #pragma unroll
        for (int k = 0; k < 4; k++) ctx[j][k] = 0.f;
    float z0 = 0.f, z1 = 0.f;

    uint32_t qhi[4][4], qlo[4][4];
    bool qloaded = false;

    for (int kt = 0; kt < S_ / KT; kt++) {
        if (kt < S_ / KT - 1) {
            const int nb = OFF_BUF + ((kt + 1) & 1) * BUF_SZ;
            const size_t rbase = (size_t)(kt + 1) * KT * DK_;
            #pragma unroll
            for (int it = 0; it < 8; it++) {
                int i = tid + it * NTHR;
                int arr = i >> 10, rem = i & 1023, row = rem >> 3, c8 = rem & 7;
                cp16(sb + (nb + arr * 9216 + row * ROWH + c8 * 8) * 2,
                     kvsrc[arr] + rbase + (size_t)row * DK_ + c8 * 8);
            }
        }
        CP_COMMIT();
        CP_WAIT1();
        __syncthreads();

        if (!qloaded) {
            qloaded = true;
            #pragma unroll
            for (int s = 0; s < 4; s++) {
                const uint32_t qa = (uint32_t)((m0 + arow) * ROWH + 16 * s + akof) * 2;
                LDSM4(qhi[s], sb + OFF_QH * 2 + qa);
                LDSM4(qlo[s], sb + OFF_QL * 2 + qa);
            }
        }

        const int bufb = OFF_BUF + (kt & 1) * BUF_SZ;
        const uint32_t kh = sb + bufb * 2;
        const uint32_t vh = sb + (bufb + 9216) * 2;

        #pragma unroll
        for (int half = 0; half < 2; half++) {
            const int rowoff = half * 64;

            // ---- GEMM1: 16x64 scores = (Qhi + Qlo) * Khi[rowoff..rowoff+64) ----
            float c[8][4];
            #pragma unroll
            for (int j = 0; j < 8; j++)
                #pragma unroll
                for (int k = 0; k < 4; k++) c[j][k] = 0.f;

            #pragma unroll
            for (int s = 0; s < 4; s++) {
                #pragma unroll
                for (int Jp = 0; Jp < 4; Jp++) {
                    const uint32_t bo =
                        (uint32_t)((rowoff + 16 * Jp + nlaneK) * ROWH + 16 * s + klaneK) * 2;
                    uint32_t kb[4];
                    LDSM4(kb, kh + bo);
                    MMA16816(c[2 * Jp],     qhi[s], kb[0], kb[1]);
                    MMA16816(c[2 * Jp + 1], qhi[s], kb[2], kb[3]);
                    MMA16816(c[2 * Jp],     qlo[s], kb[0], kb[1]);
                    MMA16816(c[2 * Jp + 1], qlo[s], kb[2], kb[3]);
                }
            }

            // ---- elt + single-term GEMM2 per k16-chunk ----
            const int mwi = 2 * kt + half;
            const unsigned long long mw0 = mbp[(size_t)gr0 * (S_ / 64) + mwi];
            const unsigned long long mw1 = mbp[(size_t)gr1 * (S_ / 64) + mwi];
            const int colbase = kt * KT + rowoff;

            #pragma unroll
            for (int s = 0; s < 4; s++) {
                uint32_t phi[4];
                #pragma unroll
                for (int jj = 0; jj < 2; jj++) {
                    const int j = 2 * s + jj;
                    const int col = 8 * j + 2 * qc;
                    float e00 = ((mw0 >> col) & 1ull)       ? __expf(c[j][0]) : 0.f;
                    float e01 = ((mw0 >> (col + 1)) & 1ull) ? __expf(c[j][1]) : 0.f;
                    float e10 = ((mw1 >> col) & 1ull)       ? __expf(c[j][2]) : 0.f;
                    float e11 = ((mw1 >> (col + 1)) & 1ull) ? __expf(c[j][3]) : 0.f;
                    z0 += e00 + e01; z1 += e10 + e11;
                    uint32_t h0 = pack2(e00, e01), h1 = pack2(e10, e11);
                    __stcg((uint32_t*)((char*)ep0 + (size_t)(colbase + col) * 2), h0);
                    __stcg((uint32_t*)((char*)ep1 + (size_t)(colbase + col) * 2), h1);
                    phi[2 * jj] = h0; phi[2 * jj + 1] = h1;
                }
                #pragma unroll
                for (int P = 0; P < 4; P++) {
                    const uint32_t vo =
                        (uint32_t)((rowoff + 16 * s + klaneV) * ROWH + 16 * P + nlaneV) * 2;
                    uint32_t vb[4];
                    LDSM4T(vb, vh + vo);
                    MMA16816(ctx[2 * P],     phi, vb[0], vb[1]);
                    MMA16816(ctx[2 * P + 1], phi, vb[2], vb[3]);
                }
            }
        }
        __syncthreads();
    }

    // ---- zinv + ctx epilogue ----
    z0 += __shfl_xor_sync(0xffffffffu, z0, 1);
    z0 += __shfl_xor_sync(0xffffffffu, z0, 2);
    z1 += __shfl_xor_sync(0xffffffffu, z1, 1);
    z1 += __shfl_xor_sync(0xffffffffu, z1, 2);
    const float zinv0 = 1.0f / z0, zinv1 = 1.0f / z1;
    if (qc == 0) { zr[m0 + r] = zinv0; zr[m0 + r + 8] = zinv1; }

    float* crow0 = ctx_out + (bh * S_ + gr0) * DK_;
    float* crow1 = ctx_out + (bh * S_ + gr1) * DK_;
    #pragma unroll
    for (int j = 0; j < 8; j++) {
        const int col = 8 * j + 2 * qc;
        __stwt((float2*)(crow0 + col), make_float2(ctx[j][0] * zinv0, ctx[j][1] * zinv0));
        __stwt((float2*)(crow1 + col), make_float2(ctx[j][2] * zinv1, ctx[j][3] * zinv1));
    }

    // ---- fused normalize: e (fp16) -> attn (fp32), this CTA's 128 rows ----
    __syncthreads();   // zr + this CTA's e-stores visible CTA-wide
    const __half* eb = g_escr + (bh * S_ + q0) * (size_t)S_;
    float* ab = attn_out + (bh * S_ + q0) * (size_t)S_;
    for (int row = 0; row < MT; row++) {
        const float zi = zr[row];
        uint4 v = __ldcs((const uint4*)(eb + (size_t)row * S_) + tid);
        float2 p0 = unpack2(v.x), p1 = unpack2(v.y), p2 = unpack2(v.z), p3 = unpack2(v.w);
        float4* a = (float4*)(ab + (size_t)row * S_) + 2 * tid;
        __stwt(a,     make_float4(p0.x * zi, p0.y * zi, p1.x * zi, p1.y * zi));
        __stwt(a + 1, make_float4(p2.x * zi, p2.y * zi, p3.x * zi, p3.y * zi));
    }
}

// ---------------- launch ----------------
extern "C" void kernel_launch(void* const* d_in, const int* in_sizes, int n_in,
                              void* d_out, int out_size) {
    (void)in_sizes; (void)n_in; (void)out_size;
    const float* Q = (const float*)d_in[0];
    const float* K = (const float*)d_in[1];
    const float* V = (const float*)d_in[2];
    const void*  mask = d_in[3];

    float* ctx_out  = (float*)d_out;
    float* attn_out = ctx_out + NEL;

    cudaFuncSetAttribute(attn_main, cudaFuncAttributeMaxDynamicSharedMemorySize, SMEM_BYTES);

    prep_kernel<<<1024, 256>>>((const float4*)Q, (const float4*)K, (const float4*)V,
                               (const unsigned int*)mask);
    dim3 grid(S_ / MT, H_, B_);
    attn_main<<<grid, NTHR, SMEM_BYTES>>>(ctx_out, attn_out);
}

// round 11
// speedup vs baseline: 1.3600x; 1.3600x over previous
#include <cuda_runtime.h>
#include <cuda_fp16.h>
#include <stdint.h>

#define B_  4
#define H_  16
#define S_  2048
#define DK_ 64
#define MT  128     // q rows per CTA
#define KT  64      // k rows per smem tile (double buffered)
#define NTHR 256    // 8 warps, 16 q-rows each
#define ROWH 72     // padded row pitch in halves (144B)

// ---------------- static scratch ----------------
#define NEL ((size_t)B_ * H_ * S_ * DK_)            // 8.4M
__device__ __align__(16) __half g_qh[NEL], g_ql[NEL];
__device__ __align__(16) __half g_kh[NEL];
__device__ __align__(16) __half g_vh[NEL];
__device__ __align__(16) __half g_escr[(size_t)B_ * H_ * S_ * S_];     // 512MB unnormalized e (fp16)
__device__ __align__(16) unsigned long long g_maskbits[(size_t)B_ * S_ * (S_ / 64)];
__device__ float g_zinv[B_ * H_ * S_];

// ---------------- helpers ----------------
__device__ __forceinline__ uint32_t pack2(float a, float b) {
    __half2 h = __floats2half2_rn(a, b);
    return *reinterpret_cast<uint32_t*>(&h);
}
__device__ __forceinline__ float2 unpack2(uint32_t u) {
    __half2 h = *reinterpret_cast<__half2*>(&u);
    return __half22float2(h);
}
__device__ __forceinline__ void cp16(uint32_t dst, const void* src) {
    asm volatile("cp.async.cg.shared.global [%0], [%1], 16;" :: "r"(dst), "l"(src));
}
#define CP_COMMIT() asm volatile("cp.async.commit_group;" ::: "memory")
#define CP_WAIT0()  asm volatile("cp.async.wait_group 0;" ::: "memory")

#define LDSM4(r, a) \
    asm volatile("ldmatrix.sync.aligned.m8n8.x4.shared.b16 {%0,%1,%2,%3}, [%4];" \
        : "=r"((r)[0]), "=r"((r)[1]), "=r"((r)[2]), "=r"((r)[3]) : "r"(a))
#define LDSM4T(r, a) \
    asm volatile("ldmatrix.sync.aligned.m8n8.x4.trans.shared.b16 {%0,%1,%2,%3}, [%4];" \
        : "=r"((r)[0]), "=r"((r)[1]), "=r"((r)[2]), "=r"((r)[3]) : "r"(a))
#define MMA16816(c, a, b0, b1) \
    asm volatile("mma.sync.aligned.m16n8k16.row.col.f32.f16.f16.f32 " \
        "{%0,%1,%2,%3},{%4,%5,%6,%7},{%8,%9},{%0,%1,%2,%3};" \
        : "+f"((c)[0]), "+f"((c)[1]), "+f"((c)[2]), "+f"((c)[3]) \
        : "r"((a)[0]), "r"((a)[1]), "r"((a)[2]), "r"((a)[3]), "r"(b0), "r"(b1))

// smem (halves): Qh | Ql | 2 x {Kh[64][72], Vh[64][72]} | e-staging (8 warps x 16 rows x 144B)
#define OFF_QH  0
#define OFF_QL  9216
#define OFF_BUF 18432
#define BUF_SZ  9216                 // halves per buffer (Kh 4608 + Vh 4608)
#define STG_BYTE ((OFF_BUF + 2 * BUF_SZ) * 2)   // 73728
#define STG_WARP 2304                // bytes per warp: 16 rows x 144B
#define SMEM_BYTES (STG_BYTE + 8 * STG_WARP)    // 92160 B -> 2 CTAs/SM fits

// ================= prep: Q -> fp16 hi/lo (x0.125), K/V -> fp16, mask -> bits ==========
__global__ void prep_kernel(const float4* __restrict__ Q, const float4* __restrict__ K,
                            const float4* __restrict__ V, const unsigned int* __restrict__ m)
{
    const int tid = threadIdx.x;
    if (blockIdx.x < 512) {
        const size_t n = NEL / 4;
        for (size_t i = (size_t)blockIdx.x * 256 + tid; i < n; i += 512 * 256) {
            float4 q = Q[i];
            q.x *= 0.125f; q.y *= 0.125f; q.z *= 0.125f; q.w *= 0.125f;
            uint32_t h0 = pack2(q.x, q.y), h1 = pack2(q.z, q.w);
            float2 a0 = unpack2(h0), a1 = unpack2(h1);
            *(uint2*)(g_qh + 4 * i) = make_uint2(h0, h1);
            *(uint2*)(g_ql + 4 * i) = make_uint2(pack2(q.x - a0.x, q.y - a0.y),
                                                 pack2(q.z - a1.x, q.w - a1.y));
            float4 k = K[i];
            *(uint2*)(g_kh + 4 * i) = make_uint2(pack2(k.x, k.y), pack2(k.z, k.w));
            float4 v = V[i];
            *(uint2*)(g_vh + 4 * i) = make_uint2(pack2(v.x, v.y), pack2(v.z, v.w));
        }
    } else {
        __shared__ int bad01_s, isfloat_s;
        if (tid == 0) { bad01_s = 0; isfloat_s = 1; }
        __syncthreads();
        int bad01 = 0;
        for (int i = tid; i < 4096; i += 256)
            if (m[i] > 1u) bad01 = 1;
        if (bad01) atomicExch(&bad01_s, 1);
        __syncthreads();
        if (bad01_s) {
            int notf = 0;
            for (int i = tid; i < 4096; i += 256) {
                unsigned v = m[i];
                if (v != 0u && v != 0x3F800000u) notf = 1;
            }
            if (notf) atomicExch(&isfloat_s, 0);
        }
        __syncthreads();
        const bool bytemask = bad01_s && !isfloat_s;
        const size_t n = (size_t)B_ * S_ * (S_ / 64);
        for (size_t i = (size_t)(blockIdx.x - 512) * 256 + tid; i < n; i += 512 * 256) {
            unsigned long long bits = 0ull;
            if (bytemask) {
                const uint4* p = (const uint4*)((const unsigned char*)m + i * 64);
                #pragma unroll
                for (int j = 0; j < 4; j++) {
                    uint4 v = p[j];
                    unsigned w[4] = {v.x, v.y, v.z, v.w};
                    #pragma unroll
                    for (int q = 0; q < 4; q++)
                        #pragma unroll
                        for (int bb = 0; bb < 4; bb++)
                            bits |= (unsigned long long)(((w[q] >> (8 * bb)) & 0xffu) == 0u)
                                    << (j * 16 + q * 4 + bb);
                }
            } else {
                const uint4* p = (const uint4*)m + i * 16;
                #pragma unroll
                for (int j = 0; j < 16; j++) {
                    uint4 v = p[j];
                    bits |= ((unsigned long long)(v.x == 0u) << (4 * j))
                          | ((unsigned long long)(v.y == 0u) << (4 * j + 1))
                          | ((unsigned long long)(v.z == 0u) << (4 * j + 2))
                          | ((unsigned long long)(v.w == 0u) << (4 * j + 3));
                }
            }
            g_maskbits[i] = bits;
        }
    }
}

// ================= mainloop: flash -> ctx + zinv + e.fp16 scratch (coalesced) =========
__global__ void __launch_bounds__(NTHR, 2)
attn_main(float* __restrict__ ctx_out)
{
    extern __shared__ __half shm[];
    const uint32_t sb = (uint32_t)__cvta_generic_to_shared(shm);

    const int tid = threadIdx.x, wid = tid >> 5, lane = tid & 31;
    const int r = lane >> 2, qc = lane & 3;
    const int m0 = 16 * wid;
    const int arow = lane & 15;
    const int akof = (lane >> 4) << 3;
    const int nlaneK = (lane & 7) + ((lane & 16) >> 1);
    const int klaneK = lane & 8;
    const int klaneV = lane & 15;
    const int nlaneV = (lane >> 4) << 3;

    const int q0 = blockIdx.x * MT;
    const size_t bh = (size_t)blockIdx.z * H_ + blockIdx.y;
    const size_t kvbase = bh * S_ * DK_;

    const int gr0 = q0 + m0 + r, gr1 = gr0 + 8;
    const unsigned long long* mbp = g_maskbits + (size_t)blockIdx.z * S_ * (S_ / 64);
    const __half* kvsrc[2] = {g_kh + kvbase, g_vh + kvbase};

    // e-staging: this warp's region, pitch 144B per row (conflict-free)
    const uint32_t stgw = sb + STG_BYTE + wid * STG_WARP;
    // writeback lanes: lane L -> row L>>1, segment L&1 (64B each)
    const int wb_row = lane >> 1, wb_seg = lane & 1;
    const uint32_t wb_saddr = stgw + wb_row * 144 + wb_seg * 64;
    __half* wb_erow = g_escr + (bh * S_ + q0 + m0 + wb_row) * (size_t)S_ + wb_seg * 32;

    // ---- prologue: issue Q + tile 0 loads, one group ----
    {
        const size_t qrow0 = bh * S_ + q0;
        #pragma unroll
        for (int it = 0; it < 8; it++) {
            int i = tid + it * NTHR;           // 0..2047: Qh then Ql
            int arr = i >> 10, rem = i & 1023, row = rem >> 3, c8 = rem & 7;
            const __half* src = (arr ? g_ql : g_qh) + (qrow0 + row) * DK_ + c8 * 8;
            cp16(sb + ((arr ? OFF_QL : OFF_QH) + row * ROWH + c8 * 8) * 2, src);
        }
        #pragma unroll
        for (int it = 0; it < 4; it++) {
            int i = tid + it * NTHR;           // 0..1023: {Kh,Vh} x 64 rows x 8 chunks
            int arr = i >> 9, rem = i & 511, row = rem >> 3, c8 = rem & 7;
            cp16(sb + (OFF_BUF + arr * 4608 + row * ROWH + c8 * 8) * 2,
                 kvsrc[arr] + (size_t)row * DK_ + c8 * 8);
        }
        CP_COMMIT();
    }

    float ctx[8][4];
    #pragma unroll
    for (int j = 0; j < 8; j++)
        #pragma unroll
        for (int k = 0; k < 4; k++) ctx[j][k] = 0.f;
    float z0 = 0.f, z1 = 0.f;

    uint32_t qhi[4][4], qlo[4][4];
    bool qloaded = false;

    for (int kt = 0; kt < S_ / KT; kt++) {
        // tile kt is ready once all pending groups complete
        CP_WAIT0();
        // barrier proves every warp finished reading buffer[(kt+1)&1] (iteration kt-1)
        __syncthreads();

        // race-free prefetch of tile kt+1 (after the barrier, overlaps tile-kt compute)
        if (kt < S_ / KT - 1) {
            const int nb = OFF_BUF + ((kt + 1) & 1) * BUF_SZ;
            const size_t rbase = (size_t)(kt + 1) * KT * DK_;
            #pragma unroll
            for (int it = 0; it < 4; it++) {
                int i = tid + it * NTHR;
                int arr = i >> 9, rem = i & 511, row = rem >> 3, c8 = rem & 7;
                cp16(sb + (nb + arr * 4608 + row * ROWH + c8 * 8) * 2,
                     kvsrc[arr] + rbase + (size_t)row * DK_ + c8 * 8);
            }
            CP_COMMIT();
        }

        if (!qloaded) {
            qloaded = true;
            #pragma unroll
            for (int s = 0; s < 4; s++) {
                const uint32_t qa = (uint32_t)((m0 + arow) * ROWH + 16 * s + akof) * 2;
                LDSM4(qhi[s], sb + OFF_QH * 2 + qa);
                LDSM4(qlo[s], sb + OFF_QL * 2 + qa);
            }
        }

        const int bufb = OFF_BUF + (kt & 1) * BUF_SZ;
        const uint32_t kh = sb + bufb * 2;
        const uint32_t vh = sb + (bufb + 4608) * 2;

        // ---- GEMM1: 16x64 scores = (Qhi + Qlo) * Khi ----
        float c[8][4];
        #pragma unroll
        for (int j = 0; j < 8; j++)
            #pragma unroll
            for (int k = 0; k < 4; k++) c[j][k] = 0.f;

        #pragma unroll
        for (int s = 0; s < 4; s++) {
            #pragma unroll
            for (int Jp = 0; Jp < 4; Jp++) {
                const uint32_t bo = (uint32_t)((16 * Jp + nlaneK) * ROWH + 16 * s + klaneK) * 2;
                uint32_t kb[4];
                LDSM4(kb, kh + bo);
                MMA16816(c[2 * Jp],     qhi[s], kb[0], kb[1]);
                MMA16816(c[2 * Jp + 1], qhi[s], kb[2], kb[3]);
                MMA16816(c[2 * Jp],     qlo[s], kb[0], kb[1]);
                MMA16816(c[2 * Jp + 1], qlo[s], kb[2], kb[3]);
            }
        }

        // ---- elt (STS into staging) + single-term GEMM2, per k16-chunk ----
        const unsigned long long mw0 = mbp[(size_t)gr0 * (S_ / 64) + kt];
        const unsigned long long mw1 = mbp[(size_t)gr1 * (S_ / 64) + kt];

        #pragma unroll
        for (int s = 0; s < 4; s++) {
            uint32_t phi[4];
            #pragma unroll
            for (int jj = 0; jj < 2; jj++) {
                const int j = 2 * s + jj;
                const int col = 8 * j + 2 * qc;
                float e00 = ((mw0 >> col) & 1ull)       ? __expf(c[j][0]) : 0.f;
                float e01 = ((mw0 >> (col + 1)) & 1ull) ? __expf(c[j][1]) : 0.f;
                float e10 = ((mw1 >> col) & 1ull)       ? __expf(c[j][2]) : 0.f;
                float e11 = ((mw1 >> (col + 1)) & 1ull) ? __expf(c[j][3]) : 0.f;
                z0 += e00 + e01; z1 += e10 + e11;
                uint32_t h0 = pack2(e00, e01), h1 = pack2(e10, e11);
                const uint32_t sa = stgw + r * 144 + col * 2;
                asm volatile("st.shared.b32 [%0], %1;" :: "r"(sa), "r"(h0));
                asm volatile("st.shared.b32 [%0], %1;" :: "r"(sa + 8 * 144), "r"(h1));
                phi[2 * jj] = h0; phi[2 * jj + 1] = h1;
            }
            #pragma unroll
            for (int P = 0; P < 4; P++) {
                const uint32_t vo = (uint32_t)((16 * s + klaneV) * ROWH + 16 * P + nlaneV) * 2;
                uint32_t vb[4];
                LDSM4T(vb, vh + vo);
                MMA16816(ctx[2 * P],     phi, vb[0], vb[1]);
                MMA16816(ctx[2 * P + 1], phi, vb[2], vb[3]);
            }
        }

        // ---- coalesced e writeback: 16 rows x 128B, 64B per lane (warp-local staging) ----
        __syncwarp();
        {
            __half* edst = wb_erow + (size_t)kt * KT;
            #pragma unroll
            for (int i = 0; i < 4; i++) {
                uint32_t x, y, zz, w;
                asm volatile("ld.shared.v4.b32 {%0,%1,%2,%3}, [%4];"
                             : "=r"(x), "=r"(y), "=r"(zz), "=r"(w) : "r"(wb_saddr + 16 * i));
                __stwt((uint4*)edst + i, make_uint4(x, y, zz, w));
            }
        }
        __syncwarp();   // writeback reads done before next iteration's STS (warp-local)
    }

    // ---- zinv + ctx epilogue ----
    z0 += __shfl_xor_sync(0xffffffffu, z0, 1);
    z0 += __shfl_xor_sync(0xffffffffu, z0, 2);
    z1 += __shfl_xor_sync(0xffffffffu, z1, 1);
    z1 += __shfl_xor_sync(0xffffffffu, z1, 2);
    const float zinv0 = 1.0f / z0, zinv1 = 1.0f / z1;
    if (qc == 0) {
        g_zinv[bh * S_ + gr0] = zinv0;
        g_zinv[bh * S_ + gr1] = zinv1;
    }

    float* crow0 = ctx_out + (bh * S_ + gr0) * DK_;
    float* crow1 = ctx_out + (bh * S_ + gr1) * DK_;
    #pragma unroll
    for (int j = 0; j < 8; j++) {
        const int col = 8 * j + 2 * qc;
        __stwt((float2*)(crow0 + col), make_float2(ctx[j][0] * zinv0, ctx[j][1] * zinv0));
        __stwt((float2*)(crow1 + col), make_float2(ctx[j][2] * zinv1, ctx[j][3] * zinv1));
    }
}

// ================= norm: e.fp16 -> attn.fp32 (pure streaming) =================
__global__ void __launch_bounds__(256)
norm_kernel(float* __restrict__ attn_out)
{
    const size_t row = blockIdx.x;               // B*H*S rows
    const float zi = g_zinv[row];
    const uint4* e = (const uint4*)(g_escr + row * (size_t)S_);
    float4* a = (float4*)(attn_out + row * (size_t)S_);
    const int t = threadIdx.x;
    uint4 v = __ldcs(e + t);                     // 8 halves
    float2 p0 = unpack2(v.x), p1 = unpack2(v.y), p2 = unpack2(v.z), p3 = unpack2(v.w);
    __stwt(a + 2 * t,     make_float4(p0.x * zi, p0.y * zi, p1.x * zi, p1.y * zi));
    __stwt(a + 2 * t + 1, make_float4(p2.x * zi, p2.y * zi, p3.x * zi, p3.y * zi));
}

// ---------------- launch ----------------
extern "C" void kernel_launch(void* const* d_in, const int* in_sizes, int n_in,
                              void* d_out, int out_size) {
    (void)in_sizes; (void)n_in; (void)out_size;
    const float* Q = (const float*)d_in[0];
    const float* K = (const float*)d_in[1];
    const float* V = (const float*)d_in[2];
    const void*  mask = d_in[3];

    float* ctx_out  = (float*)d_out;
    float* attn_out = ctx_out + NEL;

    cudaFuncSetAttribute(attn_main, cudaFuncAttributeMaxDynamicSharedMemorySize, SMEM_BYTES);

    prep_kernel<<<1024, 256>>>((const float4*)Q, (const float4*)K, (const float4*)V,
                               (const unsigned int*)mask);
    dim3 grid(S_ / MT, H_, B_);
    attn_main<<<grid, NTHR, SMEM_BYTES>>>(ctx_out);
    norm_kernel<<<B_ * H_ * S_, 256>>>(attn_out);
}

// round 12
// speedup vs baseline: 1.4150x; 1.0404x over previous
#include <cuda_runtime.h>
#include <cuda_fp16.h>
#include <stdint.h>

#define B_  4
#define H_  16
#define S_  2048
#define DK_ 64
#define MT  128     // q rows per CTA
#define KT  64      // k rows per smem tile (double buffered)
#define NTHR 256    // 8 warps, 16 q-rows each
#define ROWH 72     // padded row pitch in halves (144B)

// ---------------- static scratch ----------------
#define NEL ((size_t)B_ * H_ * S_ * DK_)            // 8.4M
__device__ __align__(16) __half g_qh[NEL], g_ql[NEL];
__device__ __align__(16) __half g_kh[NEL];
__device__ __align__(16) __half g_vh[NEL];
__device__ __align__(16) unsigned long long g_maskbits[(size_t)B_ * S_ * (S_ / 64)];

// ---------------- helpers ----------------
__device__ __forceinline__ uint32_t pack2(float a, float b) {
    __half2 h = __floats2half2_rn(a, b);
    return *reinterpret_cast<uint32_t*>(&h);
}
__device__ __forceinline__ float2 unpack2(uint32_t u) {
    __half2 h = *reinterpret_cast<__half2*>(&u);
    return __half22float2(h);
}
__device__ __forceinline__ void cp16(uint32_t dst, const void* src) {
    asm volatile("cp.async.cg.shared.global [%0], [%1], 16;" :: "r"(dst), "l"(src));
}
#define CP_COMMIT() asm volatile("cp.async.commit_group;" ::: "memory")
#define CP_WAIT0()  asm volatile("cp.async.wait_group 0;" ::: "memory")

#define LDSM4(r, a) \
    asm volatile("ldmatrix.sync.aligned.m8n8.x4.shared.b16 {%0,%1,%2,%3}, [%4];" \
        : "=r"((r)[0]), "=r"((r)[1]), "=r"((r)[2]), "=r"((r)[3]) : "r"(a))
#define LDSM4T(r, a) \
    asm volatile("ldmatrix.sync.aligned.m8n8.x4.trans.shared.b16 {%0,%1,%2,%3}, [%4];" \
        : "=r"((r)[0]), "=r"((r)[1]), "=r"((r)[2]), "=r"((r)[3]) : "r"(a))
#define MMA16816(c, a, b0, b1) \
    asm volatile("mma.sync.aligned.m16n8k16.row.col.f32.f16.f16.f32 " \
        "{%0,%1,%2,%3},{%4,%5,%6,%7},{%8,%9},{%0,%1,%2,%3};" \
        : "+f"((c)[0]), "+f"((c)[1]), "+f"((c)[2]), "+f"((c)[3]) \
        : "r"((a)[0]), "r"((a)[1]), "r"((a)[2]), "r"((a)[3]), "r"(b0), "r"(b1))

// smem (halves): Qh | Ql | 2 x {Kh[64][72], Vh[64][72]}
#define OFF_QH  0
#define OFF_QL  9216
#define OFF_BUF 18432
#define BUF_SZ  9216                 // halves per buffer (Kh 4608 + Vh 4608)
#define SMEM_BYTES ((OFF_BUF + 2 * BUF_SZ) * 2)    // 73728 B -> 2 CTAs/SM

// ================= prep: Q -> fp16 hi/lo (x0.125), K/V -> fp16, mask -> bits ==========
__global__ void prep_kernel(const float4* __restrict__ Q, const float4* __restrict__ K,
                            const float4* __restrict__ V, const unsigned int* __restrict__ m)
{
    const int tid = threadIdx.x;
    if (blockIdx.x < 512) {
        const size_t n = NEL / 4;
        for (size_t i = (size_t)blockIdx.x * 256 + tid; i < n; i += 512 * 256) {
            float4 q = Q[i];
            q.x *= 0.125f; q.y *= 0.125f; q.z *= 0.125f; q.w *= 0.125f;
            uint32_t h0 = pack2(q.x, q.y), h1 = pack2(q.z, q.w);
            float2 a0 = unpack2(h0), a1 = unpack2(h1);
            *(uint2*)(g_qh + 4 * i) = make_uint2(h0, h1);
            *(uint2*)(g_ql + 4 * i) = make_uint2(pack2(q.x - a0.x, q.y - a0.y),
                                                 pack2(q.z - a1.x, q.w - a1.y));
            float4 k = K[i];
            *(uint2*)(g_kh + 4 * i) = make_uint2(pack2(k.x, k.y), pack2(k.z, k.w));
            float4 v = V[i];
            *(uint2*)(g_vh + 4 * i) = make_uint2(pack2(v.x, v.y), pack2(v.z, v.w));
        }
    } else {
        __shared__ int bad01_s, isfloat_s;
        if (tid == 0) { bad01_s = 0; isfloat_s = 1; }
        __syncthreads();
        int bad01 = 0;
        for (int i = tid; i < 4096; i += 256)
            if (m[i] > 1u) bad01 = 1;
        if (bad01) atomicExch(&bad01_s, 1);
        __syncthreads();
        if (bad01_s) {
            int notf = 0;
            for (int i = tid; i < 4096; i += 256) {
                unsigned v = m[i];
                if (v != 0u && v != 0x3F800000u) notf = 1;
            }
            if (notf) atomicExch(&isfloat_s, 0);
        }
        __syncthreads();
        const bool bytemask = bad01_s && !isfloat_s;
        const size_t n = (size_t)B_ * S_ * (S_ / 64);
        for (size_t i = (size_t)(blockIdx.x - 512) * 256 + tid; i < n; i += 512 * 256) {
            unsigned long long bits = 0ull;
            if (bytemask) {
                const uint4* p = (const uint4*)((const unsigned char*)m + i * 64);
                #pragma unroll
                for (int j = 0; j < 4; j++) {
                    uint4 v = p[j];
                    unsigned w[4] = {v.x, v.y, v.z, v.w};
                    #pragma unroll
                    for (int q = 0; q < 4; q++)
                        #pragma unroll
                        for (int bb = 0; bb < 4; bb++)
                            bits |= (unsigned long long)(((w[q] >> (8 * bb)) & 0xffu) == 0u)
                                    << (j * 16 + q * 4 + bb);
                }
            } else {
                const uint4* p = (const uint4*)m + i * 16;
                #pragma unroll
                for (int j = 0; j < 16; j++) {
                    uint4 v = p[j];
                    bits |= ((unsigned long long)(v.x == 0u) << (4 * j))
                          | ((unsigned long long)(v.y == 0u) << (4 * j + 1))
                          | ((unsigned long long)(v.z == 0u) << (4 * j + 2))
                          | ((unsigned long long)(v.w == 0u) << (4 * j + 3));
                }
            }
            g_maskbits[i] = bits;
        }
    }
}

// ================= two-sweep mainloop: z first, then emit attn + ctx directly =========
__global__ void __launch_bounds__(NTHR, 2)
attn_main(float* __restrict__ ctx_out, float* __restrict__ attn_out)
{
    extern __shared__ __half shm[];
    const uint32_t sb = (uint32_t)__cvta_generic_to_shared(shm);

    const int tid = threadIdx.x, wid = tid >> 5, lane = tid & 31;
    const int r = lane >> 2, qc = lane & 3;
    const int m0 = 16 * wid;
    const int arow = lane & 15;
    const int akof = (lane >> 4) << 3;
    const int nlaneK = (lane & 7) + ((lane & 16) >> 1);
    const int klaneK = lane & 8;
    const int klaneV = lane & 15;
    const int nlaneV = (lane >> 4) << 3;

    const int q0 = blockIdx.x * MT;
    const size_t bh = (size_t)blockIdx.z * H_ + blockIdx.y;
    const size_t kvbase = bh * S_ * DK_;

    const int gr0 = q0 + m0 + r, gr1 = gr0 + 8;
    const unsigned long long* mbp = g_maskbits + (size_t)blockIdx.z * S_ * (S_ / 64);
    const __half* ksrc = g_kh + kvbase;
    const __half* vsrc = g_vh + kvbase;
    float* arow0 = attn_out + (bh * S_ + gr0) * (size_t)S_;
    float* arow1 = attn_out + (bh * S_ + gr1) * (size_t)S_;

    // ================= SWEEP 1: z only (K tiles, GEMM1 + masked exp) =================
    {
        const size_t qrow0 = bh * S_ + q0;
        #pragma unroll
        for (int it = 0; it < 8; it++) {
            int i = tid + it * NTHR;           // Qh then Ql
            int arr = i >> 10, rem = i & 1023, row = rem >> 3, c8 = rem & 7;
            const __half* src = (arr ? g_ql : g_qh) + (qrow0 + row) * DK_ + c8 * 8;
            cp16(sb + ((arr ? OFF_QL : OFF_QH) + row * ROWH + c8 * 8) * 2, src);
        }
        #pragma unroll
        for (int it = 0; it < 2; it++) {       // K tile 0 only: 64 rows x 8 chunks
            int i = tid + it * NTHR;
            int row = i >> 3, c8 = i & 7;
            cp16(sb + (OFF_BUF + row * ROWH + c8 * 8) * 2, ksrc + (size_t)row * DK_ + c8 * 8);
        }
        CP_COMMIT();
    }

    float z0 = 0.f, z1 = 0.f;
    uint32_t qhi[4][4], qlo[4][4];

    for (int kt = 0; kt < S_ / KT; kt++) {
        CP_WAIT0();
        __syncthreads();
        if (kt < S_ / KT - 1) {
            const int nb = OFF_BUF + ((kt + 1) & 1) * BUF_SZ;
            const size_t rbase = (size_t)(kt + 1) * KT * DK_;
            #pragma unroll
            for (int it = 0; it < 2; it++) {
                int i = tid + it * NTHR;
                int row = i >> 3, c8 = i & 7;
                cp16(sb + (nb + row * ROWH + c8 * 8) * 2, ksrc + rbase + (size_t)row * DK_ + c8 * 8);
            }
            CP_COMMIT();
        }
        if (kt == 0) {
            #pragma unroll
            for (int s = 0; s < 4; s++) {
                const uint32_t qa = (uint32_t)((m0 + arow) * ROWH + 16 * s + akof) * 2;
                LDSM4(qhi[s], sb + OFF_QH * 2 + qa);
                LDSM4(qlo[s], sb + OFF_QL * 2 + qa);
            }
        }

        const uint32_t kh = sb + (OFF_BUF + (kt & 1) * BUF_SZ) * 2;

        float c[8][4];
        #pragma unroll
        for (int j = 0; j < 8; j++)
            #pragma unroll
            for (int k = 0; k < 4; k++) c[j][k] = 0.f;
        #pragma unroll
        for (int s = 0; s < 4; s++) {
            #pragma unroll
            for (int Jp = 0; Jp < 4; Jp++) {
                const uint32_t bo = (uint32_t)((16 * Jp + nlaneK) * ROWH + 16 * s + klaneK) * 2;
                uint32_t kb[4];
                LDSM4(kb, kh + bo);
                MMA16816(c[2 * Jp],     qhi[s], kb[0], kb[1]);
                MMA16816(c[2 * Jp + 1], qhi[s], kb[2], kb[3]);
                MMA16816(c[2 * Jp],     qlo[s], kb[0], kb[1]);
                MMA16816(c[2 * Jp + 1], qlo[s], kb[2], kb[3]);
            }
        }

        const unsigned long long mw0 = mbp[(size_t)gr0 * (S_ / 64) + kt];
        const unsigned long long mw1 = mbp[(size_t)gr1 * (S_ / 64) + kt];
        #pragma unroll
        for (int j = 0; j < 8; j++) {
            const int col = 8 * j + 2 * qc;
            z0 += ((mw0 >> col) & 1ull)       ? __expf(c[j][0]) : 0.f;
            z0 += ((mw0 >> (col + 1)) & 1ull) ? __expf(c[j][1]) : 0.f;
            z1 += ((mw1 >> col) & 1ull)       ? __expf(c[j][2]) : 0.f;
            z1 += ((mw1 >> (col + 1)) & 1ull) ? __expf(c[j][3]) : 0.f;
        }
    }

    z0 += __shfl_xor_sync(0xffffffffu, z0, 1);
    z0 += __shfl_xor_sync(0xffffffffu, z0, 2);
    z1 += __shfl_xor_sync(0xffffffffu, z1, 1);
    z1 += __shfl_xor_sync(0xffffffffu, z1, 2);
    const float zinv0 = 1.0f / z0, zinv1 = 1.0f / z1;

    // ================= SWEEP 2: emit attn fp32 + ctx =================
    // buffer0 free: every warp passed kt=31's barrier (last reads of buffer0 were kt=30)
    #pragma unroll
    for (int it = 0; it < 4; it++) {           // K+V tile 0
        int i = tid + it * NTHR;
        int arr = i >> 9, rem = i & 511, row = rem >> 3, c8 = rem & 7;
        cp16(sb + (OFF_BUF + arr * 4608 + row * ROWH + c8 * 8) * 2,
             (arr ? vsrc : ksrc) + (size_t)row * DK_ + c8 * 8);
    }
    CP_COMMIT();

    float ctx[8][4];
    #pragma unroll
    for (int j = 0; j < 8; j++)
        #pragma unroll
        for (int k = 0; k < 4; k++) ctx[j][k] = 0.f;

    for (int kt = 0; kt < S_ / KT; kt++) {
        CP_WAIT0();
        __syncthreads();
        if (kt < S_ / KT - 1) {
            const int nb = OFF_BUF + ((kt + 1) & 1) * BUF_SZ;
            const size_t rbase = (size_t)(kt + 1) * KT * DK_;
            #pragma unroll
            for (int it = 0; it < 4; it++) {
                int i = tid + it * NTHR;
                int arr = i >> 9, rem = i & 511, row = rem >> 3, c8 = rem & 7;
                cp16(sb + (nb + arr * 4608 + row * ROWH + c8 * 8) * 2,
                     (arr ? vsrc : ksrc) + rbase + (size_t)row * DK_ + c8 * 8);
            }
            CP_COMMIT();
        }

        const int bufb = OFF_BUF + (kt & 1) * BUF_SZ;
        const uint32_t kh = sb + bufb * 2;
        const uint32_t vh = sb + (bufb + 4608) * 2;

        float c[8][4];
        #pragma unroll
        for (int j = 0; j < 8; j++)
            #pragma unroll
            for (int k = 0; k < 4; k++) c[j][k] = 0.f;
        #pragma unroll
        for (int s = 0; s < 4; s++) {
            #pragma unroll
            for (int Jp = 0; Jp < 4; Jp++) {
                const uint32_t bo = (uint32_t)((16 * Jp + nlaneK) * ROWH + 16 * s + klaneK) * 2;
                uint32_t kb[4];
                LDSM4(kb, kh + bo);
                MMA16816(c[2 * Jp],     qhi[s], kb[0], kb[1]);
                MMA16816(c[2 * Jp + 1], qhi[s], kb[2], kb[3]);
                MMA16816(c[2 * Jp],     qlo[s], kb[0], kb[1]);
                MMA16816(c[2 * Jp + 1], qlo[s], kb[2], kb[3]);
            }
        }

        const unsigned long long mw0 = mbp[(size_t)gr0 * (S_ / 64) + kt];
        const unsigned long long mw1 = mbp[(size_t)gr1 * (S_ / 64) + kt];
        const int colbase = kt * KT;

        #pragma unroll
        for (int s = 0; s < 4; s++) {
            uint32_t phi[4];
            #pragma unroll
            for (int jj = 0; jj < 2; jj++) {
                const int j = 2 * s + jj;
                const int col = 8 * j + 2 * qc;
                float p00 = ((mw0 >> col) & 1ull)       ? __expf(c[j][0]) * zinv0 : 0.f;
                float p01 = ((mw0 >> (col + 1)) & 1ull) ? __expf(c[j][1]) * zinv0 : 0.f;
                float p10 = ((mw1 >> col) & 1ull)       ? __expf(c[j][2]) * zinv1 : 0.f;
                float p11 = ((mw1 >> (col + 1)) & 1ull) ? __expf(c[j][3]) * zinv1 : 0.f;
                __stwt((float2*)(arow0 + colbase + col), make_float2(p00, p01));
                __stwt((float2*)(arow1 + colbase + col), make_float2(p10, p11));
                phi[2 * jj]     = pack2(p00, p01);
                phi[2 * jj + 1] = pack2(p10, p11);
            }
            #pragma unroll
            for (int P = 0; P < 4; P++) {
                const uint32_t vo = (uint32_t)((16 * s + klaneV) * ROWH + 16 * P + nlaneV) * 2;
                uint32_t vb[4];
                LDSM4T(vb, vh + vo);
                MMA16816(ctx[2 * P],     phi, vb[0], vb[1]);
                MMA16816(ctx[2 * P + 1], phi, vb[2], vb[3]);
            }
        }
    }

    // ---- ctx epilogue (already normalized via p) ----
    float* crow0 = ctx_out + (bh * S_ + gr0) * DK_;
    float* crow1 = ctx_out + (bh * S_ + gr1) * DK_;
    #pragma unroll
    for (int j = 0; j < 8; j++) {
        const int col = 8 * j + 2 * qc;
        __stwt((float2*)(crow0 + col), make_float2(ctx[j][0], ctx[j][1]));
        __stwt((float2*)(crow1 + col), make_float2(ctx[j][2], ctx[j][3]));
    }
}

// ---------------- launch ----------------
extern "C" void kernel_launch(void* const* d_in, const int* in_sizes, int n_in,
                              void* d_out, int out_size) {
    (void)in_sizes; (void)n_in; (void)out_size;
    const float* Q = (const float*)d_in[0];
    const float* K = (const float*)d_in[1];
    const float* V = (const float*)d_in[2];
    const void*  mask = d_in[3];

    float* ctx_out  = (float*)d_out;
    float* attn_out = ctx_out + NEL;

    cudaFuncSetAttribute(attn_main, cudaFuncAttributeMaxDynamicSharedMemorySize, SMEM_BYTES);

    prep_kernel<<<1024, 256>>>((const float4*)Q, (const float4*)K, (const float4*)V,
                               (const unsigned int*)mask);
    dim3 grid(S_ / MT, H_, B_);
    attn_main<<<grid, NTHR, SMEM_BYTES>>>(ctx_out, attn_out);
}

// round 13
// speedup vs baseline: 1.6276x; 1.1503x over previous
#include <cuda_runtime.h>
#include <cuda_fp16.h>
#include <stdint.h>

#define B_  4
#define H_  16
#define S_  2048
#define DK_ 64
#define MT  128     // q rows per CTA
#define KT  64      // k rows per smem tile (double buffered)
#define NTHR 256    // 8 warps, 16 q-rows each
#define ROWH 72     // padded row pitch in halves (144B)

// ---------------- static scratch ----------------
#define NEL ((size_t)B_ * H_ * S_ * DK_)            // 8.4M
__device__ __align__(16) __half g_qh[NEL], g_ql[NEL];
__device__ __align__(16) __half g_kh[NEL];
__device__ __align__(16) __half g_vh[NEL];
__device__ __align__(16) unsigned long long g_maskbits[(size_t)B_ * S_ * (S_ / 64)];

// ---------------- helpers ----------------
__device__ __forceinline__ uint32_t pack2(float a, float b) {
    __half2 h = __floats2half2_rn(a, b);
    return *reinterpret_cast<uint32_t*>(&h);
}
__device__ __forceinline__ float2 unpack2(uint32_t u) {
    __half2 h = *reinterpret_cast<__half2*>(&u);
    return __half22float2(h);
}
__device__ __forceinline__ float ex2(float x) {      // 2^x, single MUFU op
    float r;
    asm("ex2.approx.f32 %0, %1;" : "=f"(r) : "f"(x));
    return r;
}
__device__ __forceinline__ void cp16(uint32_t dst, const void* src) {
    asm volatile("cp.async.cg.shared.global [%0], [%1], 16;" :: "r"(dst), "l"(src));
}
#define CP_COMMIT() asm volatile("cp.async.commit_group;" ::: "memory")
#define CP_WAIT0()  asm volatile("cp.async.wait_group 0;" ::: "memory")

#define LDSM4(r, a) \
    asm volatile("ldmatrix.sync.aligned.m8n8.x4.shared.b16 {%0,%1,%2,%3}, [%4];" \
        : "=r"((r)[0]), "=r"((r)[1]), "=r"((r)[2]), "=r"((r)[3]) : "r"(a))
#define LDSM4T(r, a) \
    asm volatile("ldmatrix.sync.aligned.m8n8.x4.trans.shared.b16 {%0,%1,%2,%3}, [%4];" \
        : "=r"((r)[0]), "=r"((r)[1]), "=r"((r)[2]), "=r"((r)[3]) : "r"(a))
#define MMA16816(c, a, b0, b1) \
    asm volatile("mma.sync.aligned.m16n8k16.row.col.f32.f16.f16.f32 " \
        "{%0,%1,%2,%3},{%4,%5,%6,%7},{%8,%9},{%0,%1,%2,%3};" \
        : "+f"((c)[0]), "+f"((c)[1]), "+f"((c)[2]), "+f"((c)[3]) \
        : "r"((a)[0]), "r"((a)[1]), "r"((a)[2]), "r"((a)[3]), "r"(b0), "r"(b1))

// smem (halves): Qh | Ql | 2 x {Kh[64][72], Vh[64][72]}
#define OFF_QH  0
#define OFF_QL  9216
#define OFF_BUF 18432
#define BUF_SZ  9216                 // halves per buffer (Kh 4608 + Vh 4608)
#define SMEM_BYTES ((OFF_BUF + 2 * BUF_SZ) * 2)    // 73728 B -> 2 CTAs/SM

// ================= prep: Q -> fp16 hi/lo (x 0.125*log2e), K/V -> fp16, mask -> bits ====
__global__ void prep_kernel(const float4* __restrict__ Q, const float4* __restrict__ K,
                            const float4* __restrict__ V, const unsigned int* __restrict__ m)
{
    const int tid = threadIdx.x;
    if (blockIdx.x < 512) {
        // scores come out of GEMM1 as s*log2(e); exp(s) == ex2(score)
        const float QSCALE = 0.125f * 1.44269504088896340736f;
        const size_t n = NEL / 4;
        for (size_t i = (size_t)blockIdx.x * 256 + tid; i < n; i += 512 * 256) {
            float4 q = Q[i];
            q.x *= QSCALE; q.y *= QSCALE; q.z *= QSCALE; q.w *= QSCALE;
            uint32_t h0 = pack2(q.x, q.y), h1 = pack2(q.z, q.w);
            float2 a0 = unpack2(h0), a1 = unpack2(h1);
            *(uint2*)(g_qh + 4 * i) = make_uint2(h0, h1);
            *(uint2*)(g_ql + 4 * i) = make_uint2(pack2(q.x - a0.x, q.y - a0.y),
                                                 pack2(q.z - a1.x, q.w - a1.y));
            float4 k = K[i];
            *(uint2*)(g_kh + 4 * i) = make_uint2(pack2(k.x, k.y), pack2(k.z, k.w));
            float4 v = V[i];
            *(uint2*)(g_vh + 4 * i) = make_uint2(pack2(v.x, v.y), pack2(v.z, v.w));
        }
    } else {
        __shared__ int bad01_s, isfloat_s;
        if (tid == 0) { bad01_s = 0; isfloat_s = 1; }
        __syncthreads();
        int bad01 = 0;
        for (int i = tid; i < 4096; i += 256)
            if (m[i] > 1u) bad01 = 1;
        if (bad01) atomicExch(&bad01_s, 1);
        __syncthreads();
        if (bad01_s) {
            int notf = 0;
            for (int i = tid; i < 4096; i += 256) {
                unsigned v = m[i];
                if (v != 0u && v != 0x3F800000u) notf = 1;
            }
            if (notf) atomicExch(&isfloat_s, 0);
        }
        __syncthreads();
        const bool bytemask = bad01_s && !isfloat_s;
        const size_t n = (size_t)B_ * S_ * (S_ / 64);
        for (size_t i = (size_t)(blockIdx.x - 512) * 256 + tid; i < n; i += 512 * 256) {
            unsigned long long bits = 0ull;
            if (bytemask) {
                const uint4* p = (const uint4*)((const unsigned char*)m + i * 64);
                #pragma unroll
                for (int j = 0; j < 4; j++) {
                    uint4 v = p[j];
                    unsigned w[4] = {v.x, v.y, v.z, v.w};
                    #pragma unroll
                    for (int q = 0; q < 4; q++)
                        #pragma unroll
                        for (int bb = 0; bb < 4; bb++)
                            bits |= (unsigned long long)(((w[q] >> (8 * bb)) & 0xffu) == 0u)
                                    << (j * 16 + q * 4 + bb);
                }
            } else {
                const uint4* p = (const uint4*)m + i * 16;
                #pragma unroll
                for (int j = 0; j < 16; j++) {
                    uint4 v = p[j];
                    bits |= ((unsigned long long)(v.x == 0u) << (4 * j))
                          | ((unsigned long long)(v.y == 0u) << (4 * j + 1))
                          | ((unsigned long long)(v.z == 0u) << (4 * j + 2))
                          | ((unsigned long long)(v.w == 0u) << (4 * j + 3));
                }
            }
            g_maskbits[i] = bits;
        }
    }
}

// ================= two-sweep mainloop: z first, then emit attn + ctx directly =========
__global__ void __launch_bounds__(NTHR, 2)
attn_main(float* __restrict__ ctx_out, float* __restrict__ attn_out)
{
    extern __shared__ __half shm[];
    const uint32_t sb = (uint32_t)__cvta_generic_to_shared(shm);

    const int tid = threadIdx.x, wid = tid >> 5, lane = tid & 31;
    const int r = lane >> 2, qc = lane & 3;
    const int m0 = 16 * wid;
    const int arow = lane & 15;
    const int akof = (lane >> 4) << 3;
    const int nlaneK = (lane & 7) + ((lane & 16) >> 1);
    const int klaneK = lane & 8;
    const int klaneV = lane & 15;
    const int nlaneV = (lane >> 4) << 3;

    const int q0 = blockIdx.x * MT;
    const size_t bh = (size_t)blockIdx.z * H_ + blockIdx.y;
    const size_t kvbase = bh * S_ * DK_;

    const int gr0 = q0 + m0 + r, gr1 = gr0 + 8;
    const unsigned long long* mbp = g_maskbits + (size_t)blockIdx.z * S_ * (S_ / 64);
    const __half* ksrc = g_kh + kvbase;
    const __half* vsrc = g_vh + kvbase;
    float* arow0 = attn_out + (bh * S_ + gr0) * (size_t)S_;
    float* arow1 = attn_out + (bh * S_ + gr1) * (size_t)S_;

    // ================= SWEEP 1: z only (single-term GEMM1 + masked ex2) ===============
    {
        const size_t qrow0 = bh * S_ + q0;
        #pragma unroll
        for (int it = 0; it < 8; it++) {
            int i = tid + it * NTHR;           // Qh then Ql
            int arr = i >> 10, rem = i & 1023, row = rem >> 3, c8 = rem & 7;
            const __half* src = (arr ? g_ql : g_qh) + (qrow0 + row) * DK_ + c8 * 8;
            cp16(sb + ((arr ? OFF_QL : OFF_QH) + row * ROWH + c8 * 8) * 2, src);
        }
        #pragma unroll
        for (int it = 0; it < 2; it++) {       // K tile 0 only
            int i = tid + it * NTHR;
            int row = i >> 3, c8 = i & 7;
            cp16(sb + (OFF_BUF + row * ROWH + c8 * 8) * 2, ksrc + (size_t)row * DK_ + c8 * 8);
        }
        CP_COMMIT();
    }

    float z0 = 0.f, z1 = 0.f;
    uint32_t qhi[4][4], qlo[4][4];

    for (int kt = 0; kt < S_ / KT; kt++) {
        CP_WAIT0();
        __syncthreads();
        if (kt < S_ / KT - 1) {
            const int nb = OFF_BUF + ((kt + 1) & 1) * BUF_SZ;
            const size_t rbase = (size_t)(kt + 1) * KT * DK_;
            #pragma unroll
            for (int it = 0; it < 2; it++) {
                int i = tid + it * NTHR;
                int row = i >> 3, c8 = i & 7;
                cp16(sb + (nb + row * ROWH + c8 * 8) * 2, ksrc + rbase + (size_t)row * DK_ + c8 * 8);
            }
            CP_COMMIT();
        }
        if (kt == 0) {
            #pragma unroll
            for (int s = 0; s < 4; s++) {
                const uint32_t qa = (uint32_t)((m0 + arow) * ROWH + 16 * s + akof) * 2;
                LDSM4(qhi[s], sb + OFF_QH * 2 + qa);
                LDSM4(qlo[s], sb + OFF_QL * 2 + qa);
            }
        }

        const uint32_t kh = sb + (OFF_BUF + (kt & 1) * BUF_SZ) * 2;

        // single-term GEMM1: scores(log2-units) = Qhi * Khi
        float c[8][4];
        #pragma unroll
        for (int j = 0; j < 8; j++)
            #pragma unroll
            for (int k = 0; k < 4; k++) c[j][k] = 0.f;
        #pragma unroll
        for (int s = 0; s < 4; s++) {
            #pragma unroll
            for (int Jp = 0; Jp < 4; Jp++) {
                const uint32_t bo = (uint32_t)((16 * Jp + nlaneK) * ROWH + 16 * s + klaneK) * 2;
                uint32_t kb[4];
                LDSM4(kb, kh + bo);
                MMA16816(c[2 * Jp],     qhi[s], kb[0], kb[1]);
                MMA16816(c[2 * Jp + 1], qhi[s], kb[2], kb[3]);
            }
        }

        // pre-shifted mask words: per-element bits at immediate offsets 8j, 8j+1
        const unsigned long long mw0 = mbp[(size_t)gr0 * (S_ / 64) + kt] >> (2 * qc);
        const unsigned long long mw1 = mbp[(size_t)gr1 * (S_ / 64) + kt] >> (2 * qc);
        #pragma unroll
        for (int j = 0; j < 8; j++) {
            z0 += ((mw0 >> (8 * j)) & 1ull)     ? ex2(c[j][0]) : 0.f;
            z0 += ((mw0 >> (8 * j + 1)) & 1ull) ? ex2(c[j][1]) : 0.f;
            z1 += ((mw1 >> (8 * j)) & 1ull)     ? ex2(c[j][2]) : 0.f;
            z1 += ((mw1 >> (8 * j + 1)) & 1ull) ? ex2(c[j][3]) : 0.f;
        }
    }

    z0 += __shfl_xor_sync(0xffffffffu, z0, 1);
    z0 += __shfl_xor_sync(0xffffffffu, z0, 2);
    z1 += __shfl_xor_sync(0xffffffffu, z1, 1);
    z1 += __shfl_xor_sync(0xffffffffu, z1, 2);
    const float zinv0 = 1.0f / z0, zinv1 = 1.0f / z1;

    // ================= SWEEP 2: emit attn fp32 + ctx =================
    #pragma unroll
    for (int it = 0; it < 4; it++) {           // K+V tile 0
        int i = tid + it * NTHR;
        int arr = i >> 9, rem = i & 511, row = rem >> 3, c8 = rem & 7;
        cp16(sb + (OFF_BUF + arr * 4608 + row * ROWH + c8 * 8) * 2,
             (arr ? vsrc : ksrc) + (size_t)row * DK_ + c8 * 8);
    }
    CP_COMMIT();

    float ctx[8][4];
    #pragma unroll
    for (int j = 0; j < 8; j++)
        #pragma unroll
        for (int k = 0; k < 4; k++) ctx[j][k] = 0.f;

    for (int kt = 0; kt < S_ / KT; kt++) {
        CP_WAIT0();
        __syncthreads();
        if (kt < S_ / KT - 1) {
            const int nb = OFF_BUF + ((kt + 1) & 1) * BUF_SZ;
            const size_t rbase = (size_t)(kt + 1) * KT * DK_;
            #pragma unroll
            for (int it = 0; it < 4; it++) {
                int i = tid + it * NTHR;
                int arr = i >> 9, rem = i & 511, row = rem >> 3, c8 = rem & 7;
                cp16(sb + (nb + arr * 4608 + row * ROWH + c8 * 8) * 2,
                     (arr ? vsrc : ksrc) + rbase + (size_t)row * DK_ + c8 * 8);
            }
            CP_COMMIT();
        }

        const int bufb = OFF_BUF + (kt & 1) * BUF_SZ;
        const uint32_t kh = sb + bufb * 2;
        const uint32_t vh = sb + (bufb + 4608) * 2;

        // two-term GEMM1: scores(log2-units) = (Qhi + Qlo) * Khi
        float c[8][4];
        #pragma unroll
        for (int j = 0; j < 8; j++)
            #pragma unroll
            for (int k = 0; k < 4; k++) c[j][k] = 0.f;
        #pragma unroll
        for (int s = 0; s < 4; s++) {
            #pragma unroll
            for (int Jp = 0; Jp < 4; Jp++) {
                const uint32_t bo = (uint32_t)((16 * Jp + nlaneK) * ROWH + 16 * s + klaneK) * 2;
                uint32_t kb[4];
                LDSM4(kb, kh + bo);
                MMA16816(c[2 * Jp],     qhi[s], kb[0], kb[1]);
                MMA16816(c[2 * Jp + 1], qhi[s], kb[2], kb[3]);
                MMA16816(c[2 * Jp],     qlo[s], kb[0], kb[1]);
                MMA16816(c[2 * Jp + 1], qlo[s], kb[2], kb[3]);
            }
        }

        const unsigned long long mw0 = mbp[(size_t)gr0 * (S_ / 64) + kt] >> (2 * qc);
        const unsigned long long mw1 = mbp[(size_t)gr1 * (S_ / 64) + kt] >> (2 * qc);
        const int colbase = kt * KT;

        #pragma unroll
        for (int s = 0; s < 4; s++) {
            uint32_t phi[4];
            #pragma unroll
            for (int jj = 0; jj < 2; jj++) {
                const int j = 2 * s + jj;
                const int col = 8 * j + 2 * qc;
                float p00 = ((mw0 >> (8 * j)) & 1ull)     ? ex2(c[j][0]) * zinv0 : 0.f;
                float p01 = ((mw0 >> (8 * j + 1)) & 1ull) ? ex2(c[j][1]) * zinv0 : 0.f;
                float p10 = ((mw1 >> (8 * j)) & 1ull)     ? ex2(c[j][2]) * zinv1 : 0.f;
                float p11 = ((mw1 >> (8 * j + 1)) & 1ull) ? ex2(c[j][3]) * zinv1 : 0.f;
                __stwt((float2*)(arow0 + colbase + col), make_float2(p00, p01));
                __stwt((float2*)(arow1 + colbase + col), make_float2(p10, p11));
                phi[2 * jj]     = pack2(p00, p01);
                phi[2 * jj + 1] = pack2(p10, p11);
            }
            #pragma unroll
            for (int P = 0; P < 4; P++) {
                const uint32_t vo = (uint32_t)((16 * s + klaneV) * ROWH + 16 * P + nlaneV) * 2;
                uint32_t vb[4];
                LDSM4T(vb, vh + vo);
                MMA16816(ctx[2 * P],     phi, vb[0], vb[1]);
                MMA16816(ctx[2 * P + 1], phi, vb[2], vb[3]);
            }
        }
    }

    // ---- ctx epilogue (already normalized via p) ----
    float* crow0 = ctx_out + (bh * S_ + gr0) * DK_;
    float* crow1 = ctx_out + (bh * S_ + gr1) * DK_;
    #pragma unroll
    for (int j = 0; j < 8; j++) {
        const int col = 8 * j + 2 * qc;
        __stwt((float2*)(crow0 + col), make_float2(ctx[j][0], ctx[j][1]));
        __stwt((float2*)(crow1 + col), make_float2(ctx[j][2], ctx[j][3]));
    }
}

// ---------------- launch ----------------
extern "C" void kernel_launch(void* const* d_in, const int* in_sizes, int n_in,
                              void* d_out, int out_size) {
    (void)in_sizes; (void)n_in; (void)out_size;
    const float* Q = (const float*)d_in[0];
    const float* K = (const float*)d_in[1];
    const float* V = (const float*)d_in[2];
    const void*  mask = d_in[3];

    float* ctx_out  = (float*)d_out;
    float* attn_out = ctx_out + NEL;

    cudaFuncSetAttribute(attn_main, cudaFuncAttributeMaxDynamicSharedMemorySize, SMEM_BYTES);

    prep_kernel<<<1024, 256>>>((const float4*)Q, (const float4*)K, (const float4*)V,
                               (const unsigned int*)mask);
    dim3 grid(S_ / MT, H_, B_);
    attn_main<<<grid, NTHR, SMEM_BYTES>>>(ctx_out, attn_out);
}

// round 14
// speedup vs baseline: 1.7366x; 1.0669x over previous
#include <cuda_runtime.h>
#include <cuda_fp16.h>
#include <stdint.h>

#define B_  4
#define H_  16
#define S_  2048
#define DK_ 64
#define MT  128     // q rows per CTA
#define KT  64      // k rows per smem tile (double buffered)
#define NTHR 256    // 8 warps, 16 q-rows each
#define ROWH 72     // padded row pitch in halves (144B)

// ---------------- static scratch ----------------
#define NEL ((size_t)B_ * H_ * S_ * DK_)            // 8.4M
__device__ __align__(16) __half g_qh[NEL], g_ql[NEL];
__device__ __align__(16) __half g_kh[NEL];
__device__ __align__(16) __half g_vh[NEL];
__device__ __align__(16) unsigned long long g_maskbits[(size_t)B_ * S_ * (S_ / 64)];
__device__ float g_zinv[B_ * H_ * S_];

// ---------------- helpers ----------------
__device__ __forceinline__ uint32_t pack2(float a, float b) {
    __half2 h = __floats2half2_rn(a, b);
    return *reinterpret_cast<uint32_t*>(&h);
}
__device__ __forceinline__ float2 unpack2(uint32_t u) {
    __half2 h = *reinterpret_cast<__half2*>(&u);
    return __half22float2(h);
}
__device__ __forceinline__ float ex2(float x) {
    float r;
    asm("ex2.approx.f32 %0, %1;" : "=f"(r) : "f"(x));
    return r;
}
__device__ __forceinline__ void cp16(uint32_t dst, const void* src) {
    asm volatile("cp.async.cg.shared.global [%0], [%1], 16;" :: "r"(dst), "l"(src));
}
#define CP_COMMIT() asm volatile("cp.async.commit_group;" ::: "memory")
#define CP_WAIT0()  asm volatile("cp.async.wait_group 0;" ::: "memory")

#define LDSM4(r, a) \
    asm volatile("ldmatrix.sync.aligned.m8n8.x4.shared.b16 {%0,%1,%2,%3}, [%4];" \
        : "=r"((r)[0]), "=r"((r)[1]), "=r"((r)[2]), "=r"((r)[3]) : "r"(a))
#define LDSM4T(r, a) \
    asm volatile("ldmatrix.sync.aligned.m8n8.x4.trans.shared.b16 {%0,%1,%2,%3}, [%4];" \
        : "=r"((r)[0]), "=r"((r)[1]), "=r"((r)[2]), "=r"((r)[3]) : "r"(a))
#define MMA16816(c, a, b0, b1) \
    asm volatile("mma.sync.aligned.m16n8k16.row.col.f32.f16.f16.f32 " \
        "{%0,%1,%2,%3},{%4,%5,%6,%7},{%8,%9},{%0,%1,%2,%3};" \
        : "+f"((c)[0]), "+f"((c)[1]), "+f"((c)[2]), "+f"((c)[3]) \
        : "r"((a)[0]), "r"((a)[1]), "r"((a)[2]), "r"((a)[3]), "r"(b0), "r"(b1))

// ---- z-kernel smem (halves): Qh | 2 x Kh[64][72] ----
#define Z_OFF_QH  0
#define Z_OFF_BUF 9216
#define Z_BUF_SZ  4608
#define Z_SMEM_BYTES ((Z_OFF_BUF + 2 * Z_BUF_SZ) * 2)   // 36864 B -> 4 CTAs/SM

// ---- emit-kernel smem (halves): Qh | Ql | 2 x {Kh, Vh} ----
#define OFF_QH  0
#define OFF_QL  9216
#define OFF_BUF 18432
#define BUF_SZ  9216
#define SMEM_BYTES ((OFF_BUF + 2 * BUF_SZ) * 2)         // 73728 B -> 2 CTAs/SM

// ================= prep: Q -> fp16 hi/lo (x 0.125*log2e), K/V -> fp16, mask -> bits ====
__global__ void prep_kernel(const float4* __restrict__ Q, const float4* __restrict__ K,
                            const float4* __restrict__ V, const unsigned int* __restrict__ m)
{
    const int tid = threadIdx.x;
    if (blockIdx.x < 512) {
        const float QSCALE = 0.125f * 1.44269504088896340736f;
        const size_t n = NEL / 4;
        for (size_t i = (size_t)blockIdx.x * 256 + tid; i < n; i += 512 * 256) {
            float4 q = Q[i];
            q.x *= QSCALE; q.y *= QSCALE; q.z *= QSCALE; q.w *= QSCALE;
            uint32_t h0 = pack2(q.x, q.y), h1 = pack2(q.z, q.w);
            float2 a0 = unpack2(h0), a1 = unpack2(h1);
            *(uint2*)(g_qh + 4 * i) = make_uint2(h0, h1);
            *(uint2*)(g_ql + 4 * i) = make_uint2(pack2(q.x - a0.x, q.y - a0.y),
                                                 pack2(q.z - a1.x, q.w - a1.y));
            float4 k = K[i];
            *(uint2*)(g_kh + 4 * i) = make_uint2(pack2(k.x, k.y), pack2(k.z, k.w));
            float4 v = V[i];
            *(uint2*)(g_vh + 4 * i) = make_uint2(pack2(v.x, v.y), pack2(v.z, v.w));
        }
    } else {
        __shared__ int bad01_s, isfloat_s;
        if (tid == 0) { bad01_s = 0; isfloat_s = 1; }
        __syncthreads();
        int bad01 = 0;
        for (int i = tid; i < 4096; i += 256)
            if (m[i] > 1u) bad01 = 1;
        if (bad01) atomicExch(&bad01_s, 1);
        __syncthreads();
        if (bad01_s) {
            int notf = 0;
            for (int i = tid; i < 4096; i += 256) {
                unsigned v = m[i];
                if (v != 0u && v != 0x3F800000u) notf = 1;
            }
            if (notf) atomicExch(&isfloat_s, 0);
        }
        __syncthreads();
        const bool bytemask = bad01_s && !isfloat_s;
        const size_t n = (size_t)B_ * S_ * (S_ / 64);
        for (size_t i = (size_t)(blockIdx.x - 512) * 256 + tid; i < n; i += 512 * 256) {
            unsigned long long bits = 0ull;
            if (bytemask) {
                const uint4* p = (const uint4*)((const unsigned char*)m + i * 64);
                #pragma unroll
                for (int j = 0; j < 4; j++) {
                    uint4 v = p[j];
                    unsigned w[4] = {v.x, v.y, v.z, v.w};
                    #pragma unroll
                    for (int q = 0; q < 4; q++)
                        #pragma unroll
                        for (int bb = 0; bb < 4; bb++)
                            bits |= (unsigned long long)(((w[q] >> (8 * bb)) & 0xffu) == 0u)
                                    << (j * 16 + q * 4 + bb);
                }
            } else {
                const uint4* p = (const uint4*)m + i * 16;
                #pragma unroll
                for (int j = 0; j < 16; j++) {
                    uint4 v = p[j];
                    bits |= ((unsigned long long)(v.x == 0u) << (4 * j))
                          | ((unsigned long long)(v.y == 0u) << (4 * j + 1))
                          | ((unsigned long long)(v.z == 0u) << (4 * j + 2))
                          | ((unsigned long long)(v.w == 0u) << (4 * j + 3));
                }
            }
            g_maskbits[i] = bits;
        }
    }
}

// ================= z-kernel: single-term GEMM1 + masked ex2 -> g_zinv =================
__global__ void __launch_bounds__(NTHR, 4)
z_kernel()
{
    extern __shared__ __half shm[];
    const uint32_t sb = (uint32_t)__cvta_generic_to_shared(shm);

    const int tid = threadIdx.x, wid = tid >> 5, lane = tid & 31;
    const int r = lane >> 2, qc = lane & 3;
    const int m0 = 16 * wid;
    const int arow = lane & 15;
    const int akof = (lane >> 4) << 3;
    const int nlaneK = (lane & 7) + ((lane & 16) >> 1);
    const int klaneK = lane & 8;

    const int q0 = blockIdx.x * MT;
    const size_t bh = (size_t)blockIdx.z * H_ + blockIdx.y;
    const __half* ksrc = g_kh + bh * S_ * DK_;
    const int gr0 = q0 + m0 + r, gr1 = gr0 + 8;
    const unsigned long long* mbp = g_maskbits + (size_t)blockIdx.z * S_ * (S_ / 64);

    // prologue: Qh + K tile 0
    {
        const size_t qrow0 = bh * S_ + q0;
        #pragma unroll
        for (int it = 0; it < 4; it++) {
            int i = tid + it * NTHR;           // 0..1023: 128 rows x 8 chunks of Qh
            int row = i >> 3, c8 = i & 7;
            cp16(sb + (Z_OFF_QH + row * ROWH + c8 * 8) * 2,
                 g_qh + (qrow0 + row) * DK_ + c8 * 8);
        }
        #pragma unroll
        for (int it = 0; it < 2; it++) {
            int i = tid + it * NTHR;
            int row = i >> 3, c8 = i & 7;
            cp16(sb + (Z_OFF_BUF + row * ROWH + c8 * 8) * 2, ksrc + (size_t)row * DK_ + c8 * 8);
        }
        CP_COMMIT();
    }

    float z0 = 0.f, z1 = 0.f;
    uint32_t qhi[4][4];

    for (int kt = 0; kt < S_ / KT; kt++) {
        CP_WAIT0();
        __syncthreads();
        if (kt < S_ / KT - 1) {
            const int nb = Z_OFF_BUF + ((kt + 1) & 1) * Z_BUF_SZ;
            const size_t rbase = (size_t)(kt + 1) * KT * DK_;
            #pragma unroll
            for (int it = 0; it < 2; it++) {
                int i = tid + it * NTHR;
                int row = i >> 3, c8 = i & 7;
                cp16(sb + (nb + row * ROWH + c8 * 8) * 2, ksrc + rbase + (size_t)row * DK_ + c8 * 8);
            }
            CP_COMMIT();
        }
        if (kt == 0) {
            #pragma unroll
            for (int s = 0; s < 4; s++)
                LDSM4(qhi[s], sb + (uint32_t)(Z_OFF_QH + (m0 + arow) * ROWH + 16 * s + akof) * 2);
        }

        const uint32_t kh = sb + (Z_OFF_BUF + (kt & 1) * Z_BUF_SZ) * 2;

        float c[8][4];
        #pragma unroll
        for (int j = 0; j < 8; j++)
            #pragma unroll
            for (int k = 0; k < 4; k++) c[j][k] = 0.f;
        #pragma unroll
        for (int s = 0; s < 4; s++) {
            #pragma unroll
            for (int Jp = 0; Jp < 4; Jp++) {
                const uint32_t bo = (uint32_t)((16 * Jp + nlaneK) * ROWH + 16 * s + klaneK) * 2;
                uint32_t kb[4];
                LDSM4(kb, kh + bo);
                MMA16816(c[2 * Jp],     qhi[s], kb[0], kb[1]);
                MMA16816(c[2 * Jp + 1], qhi[s], kb[2], kb[3]);
            }
        }

        const unsigned long long mw0 = mbp[(size_t)gr0 * (S_ / 64) + kt] >> (2 * qc);
        const unsigned long long mw1 = mbp[(size_t)gr1 * (S_ / 64) + kt] >> (2 * qc);
        #pragma unroll
        for (int j = 0; j < 8; j++) {
            z0 += ((mw0 >> (8 * j)) & 1ull)     ? ex2(c[j][0]) : 0.f;
            z0 += ((mw0 >> (8 * j + 1)) & 1ull) ? ex2(c[j][1]) : 0.f;
            z1 += ((mw1 >> (8 * j)) & 1ull)     ? ex2(c[j][2]) : 0.f;
            z1 += ((mw1 >> (8 * j + 1)) & 1ull) ? ex2(c[j][3]) : 0.f;
        }
    }

    z0 += __shfl_xor_sync(0xffffffffu, z0, 1);
    z0 += __shfl_xor_sync(0xffffffffu, z0, 2);
    z1 += __shfl_xor_sync(0xffffffffu, z1, 1);
    z1 += __shfl_xor_sync(0xffffffffu, z1, 2);
    if (qc == 0) {
        g_zinv[bh * S_ + gr0] = 1.0f / z0;
        g_zinv[bh * S_ + gr1] = 1.0f / z1;
    }
}

// ================= emit-kernel: 2-term GEMM1 -> attn fp32 + ctx =================
__global__ void __launch_bounds__(NTHR, 2)
emit_kernel(float* __restrict__ ctx_out, float* __restrict__ attn_out)
{
    extern __shared__ __half shm[];
    const uint32_t sb = (uint32_t)__cvta_generic_to_shared(shm);

    const int tid = threadIdx.x, wid = tid >> 5, lane = tid & 31;
    const int r = lane >> 2, qc = lane & 3;
    const int m0 = 16 * wid;
    const int arow = lane & 15;
    const int akof = (lane >> 4) << 3;
    const int nlaneK = (lane & 7) + ((lane & 16) >> 1);
    const int klaneK = lane & 8;
    const int klaneV = lane & 15;
    const int nlaneV = (lane >> 4) << 3;

    const int q0 = blockIdx.x * MT;
    const size_t bh = (size_t)blockIdx.z * H_ + blockIdx.y;
    const size_t kvbase = bh * S_ * DK_;

    const int gr0 = q0 + m0 + r, gr1 = gr0 + 8;
    const unsigned long long* mbp = g_maskbits + (size_t)blockIdx.z * S_ * (S_ / 64);
    const __half* ksrc = g_kh + kvbase;
    const __half* vsrc = g_vh + kvbase;
    float* arow0 = attn_out + (bh * S_ + gr0) * (size_t)S_;
    float* arow1 = attn_out + (bh * S_ + gr1) * (size_t)S_;
    const float zinv0 = g_zinv[bh * S_ + gr0];
    const float zinv1 = g_zinv[bh * S_ + gr1];

    // prologue: Qh+Ql + K/V tile 0
    {
        const size_t qrow0 = bh * S_ + q0;
        #pragma unroll
        for (int it = 0; it < 8; it++) {
            int i = tid + it * NTHR;
            int arr = i >> 10, rem = i & 1023, row = rem >> 3, c8 = rem & 7;
            const __half* src = (arr ? g_ql : g_qh) + (qrow0 + row) * DK_ + c8 * 8;
            cp16(sb + ((arr ? OFF_QL : OFF_QH) + row * ROWH + c8 * 8) * 2, src);
        }
        #pragma unroll
        for (int it = 0; it < 4; it++) {
            int i = tid + it * NTHR;
            int arr = i >> 9, rem = i & 511, row = rem >> 3, c8 = rem & 7;
            cp16(sb + (OFF_BUF + arr * 4608 + row * ROWH + c8 * 8) * 2,
                 (arr ? vsrc : ksrc) + (size_t)row * DK_ + c8 * 8);
        }
        CP_COMMIT();
    }

    float ctx[8][4];
    #pragma unroll
    for (int j = 0; j < 8; j++)
        #pragma unroll
        for (int k = 0; k < 4; k++) ctx[j][k] = 0.f;

    uint32_t qhi[4][4], qlo[4][4];

    for (int kt = 0; kt < S_ / KT; kt++) {
        CP_WAIT0();
        __syncthreads();
        if (kt < S_ / KT - 1) {
            const int nb = OFF_BUF + ((kt + 1) & 1) * BUF_SZ;
            const size_t rbase = (size_t)(kt + 1) * KT * DK_;
            #pragma unroll
            for (int it = 0; it < 4; it++) {
                int i = tid + it * NTHR;
                int arr = i >> 9, rem = i & 511, row = rem >> 3, c8 = rem & 7;
                cp16(sb + (nb + arr * 4608 + row * ROWH + c8 * 8) * 2,
                     (arr ? vsrc : ksrc) + rbase + (size_t)row * DK_ + c8 * 8);
            }
            CP_COMMIT();
        }
        if (kt == 0) {
            #pragma unroll
            for (int s = 0; s < 4; s++) {
                const uint32_t qa = (uint32_t)((m0 + arow) * ROWH + 16 * s + akof) * 2;
                LDSM4(qhi[s], sb + OFF_QH * 2 + qa);
                LDSM4(qlo[s], sb + OFF_QL * 2 + qa);
            }
        }

        const int bufb = OFF_BUF + (kt & 1) * BUF_SZ;
        const uint32_t kh = sb + bufb * 2;
        const uint32_t vh = sb + (bufb + 4608) * 2;

        float c[8][4];
        #pragma unroll
        for (int j = 0; j < 8; j++)
            #pragma unroll
            for (int k = 0; k < 4; k++) c[j][k] = 0.f;
        #pragma unroll
        for (int s = 0; s < 4; s++) {
            #pragma unroll
            for (int Jp = 0; Jp < 4; Jp++) {
                const uint32_t bo = (uint32_t)((16 * Jp + nlaneK) * ROWH + 16 * s + klaneK) * 2;
                uint32_t kb[4];
                LDSM4(kb, kh + bo);
                MMA16816(c[2 * Jp],     qhi[s], kb[0], kb[1]);
                MMA16816(c[2 * Jp + 1], qhi[s], kb[2], kb[3]);
                MMA16816(c[2 * Jp],     qlo[s], kb[0], kb[1]);
                MMA16816(c[2 * Jp + 1], qlo[s], kb[2], kb[3]);
            }
        }

        const unsigned long long mw0 = mbp[(size_t)gr0 * (S_ / 64) + kt] >> (2 * qc);
        const unsigned long long mw1 = mbp[(size_t)gr1 * (S_ / 64) + kt] >> (2 * qc);
        const int colbase = kt * KT;

        #pragma unroll
        for (int s = 0; s < 4; s++) {
            uint32_t phi[4];
            #pragma unroll
            for (int jj = 0; jj < 2; jj++) {
                const int j = 2 * s + jj;
                const int col = 8 * j + 2 * qc;
                float p00 = ((mw0 >> (8 * j)) & 1ull)     ? ex2(c[j][0]) * zinv0 : 0.f;
                float p01 = ((mw0 >> (8 * j + 1)) & 1ull) ? ex2(c[j][1]) * zinv0 : 0.f;
                float p10 = ((mw1 >> (8 * j)) & 1ull)     ? ex2(c[j][2]) * zinv1 : 0.f;
                float p11 = ((mw1 >> (8 * j + 1)) & 1ull) ? ex2(c[j][3]) * zinv1 : 0.f;
                __stwt((float2*)(arow0 + colbase + col), make_float2(p00, p01));
                __stwt((float2*)(arow1 + colbase + col), make_float2(p10, p11));
                phi[2 * jj]     = pack2(p00, p01);
                phi[2 * jj + 1] = pack2(p10, p11);
            }
            #pragma unroll
            for (int P = 0; P < 4; P++) {
                const uint32_t vo = (uint32_t)((16 * s + klaneV) * ROWH + 16 * P + nlaneV) * 2;
                uint32_t vb[4];
                LDSM4T(vb, vh + vo);
                MMA16816(ctx[2 * P],     phi, vb[0], vb[1]);
                MMA16816(ctx[2 * P + 1], phi, vb[2], vb[3]);
            }
        }
    }

    float* crow0 = ctx_out + (bh * S_ + gr0) * DK_;
    float* crow1 = ctx_out + (bh * S_ + gr1) * DK_;
    #pragma unroll
    for (int j = 0; j < 8; j++) {
        const int col = 8 * j + 2 * qc;
        __stwt((float2*)(crow0 + col), make_float2(ctx[j][0], ctx[j][1]));
        __stwt((float2*)(crow1 + col), make_float2(ctx[j][2], ctx[j][3]));
    }
}

// ---------------- launch ----------------
extern "C" void kernel_launch(void* const* d_in, const int* in_sizes, int n_in,
                              void* d_out, int out_size) {
    (void)in_sizes; (void)n_in; (void)out_size;
    const float* Q = (const float*)d_in[0];
    const float* K = (const float*)d_in[1];
    const float* V = (const float*)d_in[2];
    const void*  mask = d_in[3];

    float* ctx_out  = (float*)d_out;
    float* attn_out = ctx_out + NEL;

    cudaFuncSetAttribute(z_kernel, cudaFuncAttributeMaxDynamicSharedMemorySize, Z_SMEM_BYTES);
    cudaFuncSetAttribute(emit_kernel, cudaFuncAttributeMaxDynamicSharedMemorySize, SMEM_BYTES);

    prep_kernel<<<1024, 256>>>((const float4*)Q, (const float4*)K, (const float4*)V,
                               (const unsigned int*)mask);
    dim3 grid(S_ / MT, H_, B_);
    z_kernel<<<grid, NTHR, Z_SMEM_BYTES>>>();
    emit_kernel<<<grid, NTHR, SMEM_BYTES>>>(ctx_out, attn_out);
}